// round 10
// baseline (speedup 1.0000x reference)
#include <cuda_runtime.h>
#include <math.h>
#include <stdint.h>

#define BB   2
#define LL   4096
#define HH   2048
#define DKK  128
#define CCH  64          // chunk length C
#define NCC  64          // chunks per batch
#define NTOK (BB*LL)     // 8192 tokens

// ---------------- scratch (static device globals; no allocation) ----------------
__device__ __align__(16) float g_qe[BB*LL*DKK];                 // q * exp(B)
__device__ __align__(16) float g_kd[BB*LL*DKK];                 // k * exp(Blast - B)
__device__ __align__(16) float g_eL[BB*NCC*DKK];                // exp(Blast)
__device__ __align__(16) float g_A [BB*NCC*CCH*CCH];            // intra-chunk A (tril)
__device__ __align__(16) float g_o [(size_t)NTOK*HH];           // GLA output, later h
__device__ __align__(16) float g_go[(size_t)NTOK*HH];           // gate pre-activation
__device__ __align__(16) float g_qk[(size_t)NTOK*256];          // q/k logits (ldc=256)

// ================================ helpers ========================================
__device__ __forceinline__ float tf32r(float x) {
    uint32_t o;
    asm("cvt.rna.tf32.f32 %0, %1;" : "=r"(o) : "f"(x));
    return __uint_as_float(o);
}
__device__ __forceinline__ float4 ld4tf(const float* p) {
    float4 v = *(const float4*)p;
    v.x = tf32r(v.x); v.y = tf32r(v.y); v.z = tf32r(v.z); v.w = tf32r(v.w);
    return v;
}

// D += A*B : m16n8k8 tf32 (sm_80+ PTX, runs on plain sm_103)
__device__ __forceinline__ void mma16n8k8(float d[4],
                                          uint32_t a0, uint32_t a1, uint32_t a2, uint32_t a3,
                                          uint32_t b0, uint32_t b1) {
    asm("mma.sync.aligned.m16n8k8.row.col.f32.tf32.tf32.f32 "
        "{%0,%1,%2,%3}, {%4,%5,%6,%7}, {%8,%9}, {%0,%1,%2,%3};"
        : "+f"(d[0]), "+f"(d[1]), "+f"(d[2]), "+f"(d[3])
        : "r"(a0), "r"(a1), "r"(a2), "r"(a3), "r"(b0), "r"(b1));
}

#define SK 24

// =================================================================================
// BIG tf32 GEMM: CTA tile 128x256, BK=16, 8 warps (2x4), warp tile 64x64.
// smem m-major permuted-k (fragment pair adjacent), row stride SK=24.
// Dual-K source: A/B switch at ktile 128. Loader applies cvt.rna.tf32.
// Dynamic smem: (2*128 + 2*256) * SK * 4 = 73728 bytes.
// =================================================================================
#define BIG_SMEM ((2*128 + 2*256)*SK*4)

__global__ void __launch_bounds__(256, 1) gemm_big_kernel(
    const float* __restrict__ A1, const float* __restrict__ B1,
    const float* __restrict__ A2, const float* __restrict__ B2,
    float* __restrict__ Cmat, int nk, int ldc)
{
    extern __shared__ float sm[];
    // As stage s: sm + s*128*SK ; Bs stage s: sm + 2*128*SK + s*256*SK
    float* Asm[2] = { sm,            sm + 128*SK };
    float* Bsm[2] = { sm + 256*SK,   sm + 256*SK + 256*SK };

    const int tid = threadIdx.x;
    const int m0 = blockIdx.y * 128;
    const int n0 = blockIdx.x * 256;
    const int row = tid >> 2;            // 0..63
    const int kk4 = (tid & 3) << 2;      // 0,4,8,12
    const int pbase = ((kk4 >> 2) & 1) + (kk4 & 8);
    const int warp = tid >> 5, lane = tid & 31;
    const int wm = (warp & 1) * 64;
    const int wn = (warp >> 1) * 64;
    const int g = lane >> 2, t = lane & 3;

    float acc[4][8][4];
#pragma unroll
    for (int i = 0; i < 4; i++)
#pragma unroll
        for (int j = 0; j < 8; j++)
#pragma unroll
            for (int k = 0; k < 4; k++) acc[i][j][k] = 0.f;

    float4 ra0, ra1, rb0, rb1, rb2, rb3;

    // ---- load ktile 0 ----
    {
        const float* Ab = A1 + (size_t)(m0 + row) * HH + kk4;
        const float* Bb = B1 + (size_t)(n0 + row) * HH + kk4;
        ra0 = ld4tf(Ab);
        ra1 = ld4tf(Ab + (size_t)64 * HH);
        rb0 = ld4tf(Bb);
        rb1 = ld4tf(Bb + (size_t)64 * HH);
        rb2 = ld4tf(Bb + (size_t)128 * HH);
        rb3 = ld4tf(Bb + (size_t)192 * HH);
    }
#pragma unroll
    for (int j = 0; j < 4; j++) {
        Asm[0][(row)*SK     + pbase + 2*j] = ((float*)&ra0)[j];
        Asm[0][(row+64)*SK  + pbase + 2*j] = ((float*)&ra1)[j];
        Bsm[0][(row)*SK     + pbase + 2*j] = ((float*)&rb0)[j];
        Bsm[0][(row+64)*SK  + pbase + 2*j] = ((float*)&rb1)[j];
        Bsm[0][(row+128)*SK + pbase + 2*j] = ((float*)&rb2)[j];
        Bsm[0][(row+192)*SK + pbase + 2*j] = ((float*)&rb3)[j];
    }
    __syncthreads();

    for (int kt = 0; kt < nk; kt++) {
        const int cur = kt & 1;
        if (kt + 1 < nk) {
            int nx = kt + 1;
            const float* Ab; const float* Bb;
            if (nx < 128) { Ab = A1; Bb = B1; } else { Ab = A2; Bb = B2; }
            int kof = (nx & 127) * 16 + kk4;
            Ab += (size_t)(m0 + row) * HH + kof;
            Bb += (size_t)(n0 + row) * HH + kof;
            ra0 = ld4tf(Ab);
            ra1 = ld4tf(Ab + (size_t)64 * HH);
            rb0 = ld4tf(Bb);
            rb1 = ld4tf(Bb + (size_t)64 * HH);
            rb2 = ld4tf(Bb + (size_t)128 * HH);
            rb3 = ld4tf(Bb + (size_t)192 * HH);
        }

        const float* Ac = Asm[cur];
        const float* Bc = Bsm[cur];
#pragma unroll
        for (int ks = 0; ks < 2; ks++) {
            const int kb = ks*8 + 2*t;
            uint32_t a[4][4];
#pragma unroll
            for (int mt = 0; mt < 4; mt++) {
                int r = wm + mt*16 + g;
                float2 lo = *(const float2*)&Ac[r*SK + kb];
                float2 hi = *(const float2*)&Ac[(r+8)*SK + kb];
                a[mt][0] = __float_as_uint(lo.x);
                a[mt][1] = __float_as_uint(hi.x);
                a[mt][2] = __float_as_uint(lo.y);
                a[mt][3] = __float_as_uint(hi.y);
            }
            uint32_t b[8][2];
#pragma unroll
            for (int nt = 0; nt < 8; nt++) {
                int c = wn + nt*8 + g;
                float2 bb = *(const float2*)&Bc[c*SK + kb];
                b[nt][0] = __float_as_uint(bb.x);
                b[nt][1] = __float_as_uint(bb.y);
            }
#pragma unroll
            for (int mt = 0; mt < 4; mt++)
#pragma unroll
                for (int nt = 0; nt < 8; nt++)
                    mma16n8k8(acc[mt][nt],
                              a[mt][0], a[mt][1], a[mt][2], a[mt][3],
                              b[nt][0], b[nt][1]);
        }

        if (kt + 1 < nk) {
            const int nxt = cur ^ 1;
#pragma unroll
            for (int j = 0; j < 4; j++) {
                Asm[nxt][(row)*SK     + pbase + 2*j] = ((float*)&ra0)[j];
                Asm[nxt][(row+64)*SK  + pbase + 2*j] = ((float*)&ra1)[j];
                Bsm[nxt][(row)*SK     + pbase + 2*j] = ((float*)&rb0)[j];
                Bsm[nxt][(row+64)*SK  + pbase + 2*j] = ((float*)&rb1)[j];
                Bsm[nxt][(row+128)*SK + pbase + 2*j] = ((float*)&rb2)[j];
                Bsm[nxt][(row+192)*SK + pbase + 2*j] = ((float*)&rb3)[j];
            }
        }
        __syncthreads();
    }

    // ---- epilogue ----
#pragma unroll
    for (int mt = 0; mt < 4; mt++) {
        int r0 = m0 + wm + mt*16 + g;
#pragma unroll
        for (int nt = 0; nt < 8; nt++) {
            int c = n0 + wn + nt*8 + 2*t;
            *(float2*)(Cmat + (size_t)r0*ldc + c) =
                make_float2(acc[mt][nt][0], acc[mt][nt][1]);
            *(float2*)(Cmat + (size_t)(r0+8)*ldc + c) =
                make_float2(acc[mt][nt][2], acc[mt][nt][3]);
        }
    }
}

// =================================================================================
// Small tf32 GEMM (projections): CTA 128x128, 8 warps 64x32, dual-N:
// B selected by blockIdx.x (B1/B2), C col base = blockIdx.x*128.
// =================================================================================
__global__ void __launch_bounds__(256) gemm_proj_kernel(
    const float* __restrict__ A1, const float* __restrict__ B1,
    const float* __restrict__ B2,
    float* __restrict__ Cmat, int nk, int ldc)
{
    __shared__ float As[2][128*SK];
    __shared__ float Bs[2][128*SK];

    const int tid = threadIdx.x;
    const int m0 = blockIdx.y * 128;
    const int co = blockIdx.x * 128;
    const float* Bsel = blockIdx.x ? B2 : B1;
    const int row = tid >> 2;
    const int kk4 = (tid & 3) << 2;
    const int pbase = ((kk4 >> 2) & 1) + (kk4 & 8);
    const int warp = tid >> 5, lane = tid & 31;
    const int wm = (warp & 1) * 64;
    const int wn = (warp >> 1) * 32;
    const int g = lane >> 2, t = lane & 3;

    float acc[4][4][4];
#pragma unroll
    for (int i = 0; i < 4; i++)
#pragma unroll
        for (int j = 0; j < 4; j++)
#pragma unroll
            for (int k = 0; k < 4; k++) acc[i][j][k] = 0.f;

    float4 ra0, ra1, rb0, rb1;
    {
        const float* Ab = A1 + (size_t)(m0 + row) * HH + kk4;
        const float* Bb = Bsel + (size_t)row * HH + kk4;
        ra0 = ld4tf(Ab);
        ra1 = ld4tf(Ab + (size_t)64 * HH);
        rb0 = ld4tf(Bb);
        rb1 = ld4tf(Bb + (size_t)64 * HH);
    }
#pragma unroll
    for (int j = 0; j < 4; j++) {
        As[0][(row)*SK    + pbase + 2*j] = ((float*)&ra0)[j];
        As[0][(row+64)*SK + pbase + 2*j] = ((float*)&ra1)[j];
        Bs[0][(row)*SK    + pbase + 2*j] = ((float*)&rb0)[j];
        Bs[0][(row+64)*SK + pbase + 2*j] = ((float*)&rb1)[j];
    }
    __syncthreads();

    for (int kt = 0; kt < nk; kt++) {
        const int cur = kt & 1;
        if (kt + 1 < nk) {
            int kof = (kt + 1) * 16 + kk4;
            const float* Ab = A1 + (size_t)(m0 + row) * HH + kof;
            const float* Bb = Bsel + (size_t)row * HH + kof;
            ra0 = ld4tf(Ab);
            ra1 = ld4tf(Ab + (size_t)64 * HH);
            rb0 = ld4tf(Bb);
            rb1 = ld4tf(Bb + (size_t)64 * HH);
        }

#pragma unroll
        for (int ks = 0; ks < 2; ks++) {
            const int kb = ks*8 + 2*t;
            uint32_t a[4][4];
#pragma unroll
            for (int mt = 0; mt < 4; mt++) {
                int r = wm + mt*16 + g;
                float2 lo = *(const float2*)&As[cur][r*SK + kb];
                float2 hi = *(const float2*)&As[cur][(r+8)*SK + kb];
                a[mt][0] = __float_as_uint(lo.x);
                a[mt][1] = __float_as_uint(hi.x);
                a[mt][2] = __float_as_uint(lo.y);
                a[mt][3] = __float_as_uint(hi.y);
            }
            uint32_t b[4][2];
#pragma unroll
            for (int nt = 0; nt < 4; nt++) {
                int c = wn + nt*8 + g;
                float2 bb = *(const float2*)&Bs[cur][c*SK + kb];
                b[nt][0] = __float_as_uint(bb.x);
                b[nt][1] = __float_as_uint(bb.y);
            }
#pragma unroll
            for (int mt = 0; mt < 4; mt++)
#pragma unroll
                for (int nt = 0; nt < 4; nt++)
                    mma16n8k8(acc[mt][nt],
                              a[mt][0], a[mt][1], a[mt][2], a[mt][3],
                              b[nt][0], b[nt][1]);
        }

        if (kt + 1 < nk) {
            const int nxt = cur ^ 1;
#pragma unroll
            for (int j = 0; j < 4; j++) {
                As[nxt][(row)*SK    + pbase + 2*j] = ((float*)&ra0)[j];
                As[nxt][(row+64)*SK + pbase + 2*j] = ((float*)&ra1)[j];
                Bs[nxt][(row)*SK    + pbase + 2*j] = ((float*)&rb0)[j];
                Bs[nxt][(row+64)*SK + pbase + 2*j] = ((float*)&rb1)[j];
            }
        }
        __syncthreads();
    }

#pragma unroll
    for (int mt = 0; mt < 4; mt++) {
        int r0 = m0 + wm + mt*16 + g;
#pragma unroll
        for (int nt = 0; nt < 4; nt++) {
            int c = co + wn + nt*8 + 2*t;
            *(float2*)(Cmat + (size_t)r0*ldc + c) =
                make_float2(acc[mt][nt][0], acc[mt][nt][1]);
            *(float2*)(Cmat + (size_t)(r0+8)*ldc + c) =
                make_float2(acc[mt][nt][2], acc[mt][nt][3]);
        }
    }
}

// =================================================================================
// gate_kernel — per chunk: softmax(q) / sigmoid(k) / cumsum B, qe/kd/eL outputs,
// and A = (q e^{B-Bmid}) @ (k e^{Bmid-B})^T with tril mask.  grid = 128 blocks.
// =================================================================================
#define PADG 129
#define GATE_FLOATS (3*64*PADG + 3*128)
#define GATE_BYTES  (GATE_FLOATS*4)

__global__ void __launch_bounds__(256) gate_kernel()
{
    extern __shared__ float sm[];
    float* ql   = sm;                 // 64*PADG
    float* kl   = sm + 64*PADG;       // 64*PADG
    float* bs   = sm + 2*64*PADG;     // 64*PADG
    float* bmid = sm + 3*64*PADG;     // 128
    float* eBm  = bmid + 128;         // 128
    float* eBlm = bmid + 256;         // 128

    const int blk = blockIdx.x;
    const int b = blk / NCC, c = blk % NCC;
    const int tid = threadIdx.x;
    const int r0 = b*LL + c*CCH;

    for (int idx = tid; idx < 64*128; idx += 256) {
        int t = idx >> 7, d = idx & 127;
        const float* gr = g_qk + (size_t)(r0 + t) * 256;
        ql[t*PADG + d] = gr[d];
        kl[t*PADG + d] = 1.f / (1.f + __expf(-gr[128 + d]));
    }
    __syncthreads();

    if (tid < 64) {
        float* r = ql + tid*PADG;
        float m = -1e30f;
        for (int d = 0; d < 128; d++) m = fmaxf(m, r[d]);
        float s = 0.f;
        for (int d = 0; d < 128; d++) { float e = __expf(r[d] - m); r[d] = e; s += e; }
        float inv = 1.f / s;
        for (int d = 0; d < 128; d++) r[d] *= inv;
    }
    if (tid >= 128) {
        int d = tid - 128;
        float acc = 0.f;
        for (int t = 0; t < 64; t++) {
            acc += -log1pf(__expf(kl[t*PADG + d]));
            bs[t*PADG + d] = acc;
        }
        float Bm = bs[31*PADG + d];
        bmid[d] = Bm;
        eBm[d]  = __expf(Bm);
        eBlm[d] = __expf(acc - Bm);
        g_eL[blk*128 + d] = __expf(acc);
    }
    __syncthreads();

    size_t gbase = (size_t)r0 * DKK;
    for (int idx = tid; idx < 64*128; idx += 256) {
        int t = idx >> 7, d = idx & 127;
        float bv = bs[t*PADG + d] - bmid[d];
        float e1 = __expf(bv);
        float e2 = __expf(-bv);
        float q2 = ql[t*PADG + d] * e1;
        float k2 = kl[t*PADG + d] * e2;
        ql[t*PADG + d] = q2;
        kl[t*PADG + d] = k2;
        g_qe[gbase + idx] = q2 * eBm[d];
        g_kd[gbase + idx] = k2 * eBlm[d];
    }
    __syncthreads();

    const int tr = (tid >> 4) * 4;
    const int tc = (tid & 15) * 4;
    float a4[4][4];
#pragma unroll
    for (int r = 0; r < 4; r++)
#pragma unroll
        for (int cc = 0; cc < 4; cc++) a4[r][cc] = 0.f;
    for (int d = 0; d < 128; d++) {
        float qv[4], kv[4];
#pragma unroll
        for (int r = 0; r < 4; r++)  qv[r]  = ql[(tr+r)*PADG + d];
#pragma unroll
        for (int cc = 0; cc < 4; cc++) kv[cc] = kl[(tc+cc)*PADG + d];
#pragma unroll
        for (int r = 0; r < 4; r++)
#pragma unroll
            for (int cc = 0; cc < 4; cc++) a4[r][cc] += qv[r]*kv[cc];
    }
    float* Ag = g_A + (size_t)blk * CCH * CCH;
#pragma unroll
    for (int r = 0; r < 4; r++)
#pragma unroll
        for (int cc = 0; cc < 4; cc++)
            Ag[(tr+r)*64 + tc+cc] = (tr+r >= tc+cc) ? a4[r][cc] : 0.f;
}

// =================================================================================
// recurrence: chunked GLA. grid (H/32, B), 256 threads.
// =================================================================================
#define SMEM2_FLOATS (8192 + 8192 + 4096 + 2048 + 4096 + 128)
#define SMEM2_BYTES  (SMEM2_FLOATS*4)

__global__ void __launch_bounds__(256) recurrence_kernel(const float* __restrict__ x)
{
    extern __shared__ float sm[];
    float* qe_s = sm;              // 64*128
    float* kd_s = sm + 8192;       // 64*128
    float* A_s  = sm + 16384;      // 64*64
    float* v_s  = sm + 20480;      // 64*32
    float* S_s  = sm + 22528;      // 128*32
    float* eL_s = sm + 26624;      // 128

    const int b  = blockIdx.y;
    const int v0 = blockIdx.x * 32;
    const int tid = threadIdx.x;
    const int tx = tid & 15;
    const int ty = tid >> 4;
    const int vv = 2*tx;

    for (int i = tid; i < 128*32; i += 256) S_s[i] = 0.f;

    for (int c = 0; c < NCC; c++) {
        __syncthreads();
        {
            size_t base = ((size_t)(b*LL + c*CCH)) * DKK;
            for (int idx = tid*4; idx < 8192; idx += 1024) {
                *(float4*)(qe_s + idx) = *(const float4*)(g_qe + base + idx);
                *(float4*)(kd_s + idx) = *(const float4*)(g_kd + base + idx);
            }
            const float* Ag = g_A + (size_t)(b*NCC + c) * 4096;
            for (int idx = tid*4; idx < 4096; idx += 1024)
                *(float4*)(A_s + idx) = *(const float4*)(Ag + idx);
            for (int idx = tid; idx < 64*32; idx += 256) {
                int t = idx >> 5, j = idx & 31;
                v_s[idx] = x[((size_t)(b*LL + c*CCH + t)) * HH + v0 + j];
            }
            if (tid < 128) eL_s[tid] = g_eL[(b*NCC + c)*128 + tid];
        }
        __syncthreads();

        float o0[4] = {0,0,0,0}, o1[4] = {0,0,0,0};
#pragma unroll 4
        for (int j = 0; j < 64; j += 4) {
            float2 vj0 = *(float2*)(v_s + (j+0)*32 + vv);
            float2 vj1 = *(float2*)(v_s + (j+1)*32 + vv);
            float2 vj2 = *(float2*)(v_s + (j+2)*32 + vv);
            float2 vj3 = *(float2*)(v_s + (j+3)*32 + vv);
#pragma unroll
            for (int r = 0; r < 4; r++) {
                float4 a = *(float4*)(A_s + (ty + 16*r)*64 + j);
                o0[r] += a.x*vj0.x + a.y*vj1.x + a.z*vj2.x + a.w*vj3.x;
                o1[r] += a.x*vj0.y + a.y*vj1.y + a.z*vj2.y + a.w*vj3.y;
            }
        }
#pragma unroll 4
        for (int d = 0; d < 128; d += 4) {
            float2 s0 = *(float2*)(S_s + (d+0)*32 + vv);
            float2 s1 = *(float2*)(S_s + (d+1)*32 + vv);
            float2 s2 = *(float2*)(S_s + (d+2)*32 + vv);
            float2 s3 = *(float2*)(S_s + (d+3)*32 + vv);
#pragma unroll
            for (int r = 0; r < 4; r++) {
                float4 q = *(float4*)(qe_s + (ty + 16*r)*128 + d);
                o0[r] += q.x*s0.x + q.y*s1.x + q.z*s2.x + q.w*s3.x;
                o1[r] += q.x*s0.y + q.y*s1.y + q.z*s2.y + q.w*s3.y;
            }
        }
#pragma unroll
        for (int r = 0; r < 4; r++) {
            size_t row = (size_t)(b*LL + c*CCH + ty + 16*r);
            *(float2*)(g_o + row*HH + v0 + vv) = make_float2(o0[r], o1[r]);
        }

        float a0[8] = {0,0,0,0,0,0,0,0}, a1[8] = {0,0,0,0,0,0,0,0};
        for (int j = 0; j < 64; j++) {
            float2 vj = *(float2*)(v_s + j*32 + vv);
            float4 k0 = *(float4*)(kd_s + j*128 + ty*8);
            float4 k1 = *(float4*)(kd_s + j*128 + ty*8 + 4);
            a0[0] += k0.x*vj.x; a1[0] += k0.x*vj.y;
            a0[1] += k0.y*vj.x; a1[1] += k0.y*vj.y;
            a0[2] += k0.z*vj.x; a1[2] += k0.z*vj.y;
            a0[3] += k0.w*vj.x; a1[3] += k0.w*vj.y;
            a0[4] += k1.x*vj.x; a1[4] += k1.x*vj.y;
            a0[5] += k1.y*vj.x; a1[5] += k1.y*vj.y;
            a0[6] += k1.z*vj.x; a1[6] += k1.z*vj.y;
            a0[7] += k1.w*vj.x; a1[7] += k1.w*vj.y;
        }
        __syncthreads();
#pragma unroll
        for (int dd = 0; dd < 8; dd++) {
            int d = ty*8 + dd;
            float e = eL_s[d];
            S_s[d*32 + vv]     = S_s[d*32 + vv]     * e + a0[dd];
            S_s[d*32 + vv + 1] = S_s[d*32 + vv + 1] * e + a1[dd];
        }
    }
}

// =================================================================================
// rms_silu: h = rmsnorm(o)*g * silu(go)  (in-place into g_o)
// =================================================================================
__global__ void __launch_bounds__(256) rms_silu_kernel(const float* __restrict__ gnw)
{
    __shared__ float red[256];
    const size_t row = blockIdx.x;
    float* orow  = g_o  + row * HH;
    const float* gorow = g_go + row * HH;
    const int tid = threadIdx.x;

    float s = 0.f;
#pragma unroll
    for (int i = tid; i < HH/4; i += 256) {
        float4 v = ((const float4*)orow)[i];
        s += v.x*v.x + v.y*v.y + v.z*v.z + v.w*v.w;
    }
    red[tid] = s;
    __syncthreads();
    for (int off = 128; off > 0; off >>= 1) {
        if (tid < off) red[tid] += red[tid + off];
        __syncthreads();
    }
    float rinv = rsqrtf(red[0] * (1.f / (float)HH) + 1e-5f);

#pragma unroll
    for (int i = tid; i < HH/4; i += 256) {
        float4 ov = ((const float4*)orow)[i];
        float4 gv = ((const float4*)gorow)[i];
        float4 wv = ((const float4*)gnw)[i];
        float4 o4;
        { float a = ov.x * rinv * wv.x, g = gv.x; o4.x = a * (g / (1.f + __expf(-g))); }
        { float a = ov.y * rinv * wv.y, g = gv.y; o4.y = a * (g / (1.f + __expf(-g))); }
        { float a = ov.z * rinv * wv.z, g = gv.z; o4.z = a * (g / (1.f + __expf(-g))); }
        { float a = ov.w * rinv * wv.w, g = gv.w; o4.w = a * (g / (1.f + __expf(-g))); }
        ((float4*)orow)[i] = o4;
    }
}

// ================================= host side =====================================
extern "C" void kernel_launch(void* const* d_in, const int* in_sizes, int n_in,
                              void* d_out, int out_size)
{
    const float* x   = (const float*)d_in[0];
    const float* Wq  = (const float*)d_in[1];
    const float* Wk  = (const float*)d_in[2];
    const float* Wog = (const float*)d_in[3];
    const float* Wig = (const float*)d_in[4];
    const float* Wo  = (const float*)d_in[5];
    const float* gnw = (const float*)d_in[6];
    float* out = (float*)d_out;

    cudaFuncSetAttribute(gate_kernel,
                         cudaFuncAttributeMaxDynamicSharedMemorySize, GATE_BYTES);
    cudaFuncSetAttribute(recurrence_kernel,
                         cudaFuncAttributeMaxDynamicSharedMemorySize, SMEM2_BYTES);
    cudaFuncSetAttribute(gemm_big_kernel,
                         cudaFuncAttributeMaxDynamicSharedMemorySize, BIG_SMEM);

    float *p_o, *p_go, *p_qk;
    cudaGetSymbolAddress((void**)&p_o,  g_o);
    cudaGetSymbolAddress((void**)&p_go, g_go);
    cudaGetSymbolAddress((void**)&p_qk, g_qk);

    // 1) q/k logits: ql = x@Wq^T, kl = x@Wk^T  (dual-N projection GEMM)
    gemm_proj_kernel<<<dim3(2, NTOK/128), 256>>>(x, Wq, Wk, p_qk, 128, 256);
    // 2) gating precompute + intra-chunk A
    gate_kernel<<<BB*NCC, 256, GATE_BYTES>>>();
    // 3) chunked recurrence -> g_o
    recurrence_kernel<<<dim3(HH/32, BB), 256, SMEM2_BYTES>>>(x);
    // 4) go = x @ Wig^T + o @ Wog^T  (one dual-K big GEMM, K=4096)
    gemm_big_kernel<<<dim3(HH/256, NTOK/128), 256, BIG_SMEM>>>(x, Wig, p_o, Wog, p_go, 256, HH);
    // 5) h = rmsnorm(o)*g * silu(go)  (in place)
    rms_silu_kernel<<<NTOK, 256>>>(gnw);
    // 6) out = h @ Wo^T
    gemm_big_kernel<<<dim3(HH/256, NTOK/128), 256, BIG_SMEM>>>(p_o, Wo, p_o, Wo, out, 128, HH);
}

// round 11
// speedup vs baseline: 1.0114x; 1.0114x over previous
#include <cuda_runtime.h>
#include <math.h>
#include <stdint.h>

#define BB   2
#define LL   4096
#define HH   2048
#define DKK  128
#define CCH  64          // chunk length C
#define NCC  64          // chunks per batch
#define NTOK (BB*LL)     // 8192 tokens

// ---------------- scratch (static device globals; no allocation) ----------------
__device__ __align__(16) float g_qe[BB*LL*DKK];                 // q * exp(B)
__device__ __align__(16) float g_kd[BB*LL*DKK];                 // k * exp(Blast - B)
__device__ __align__(16) float g_eL[BB*NCC*DKK];                // exp(Blast)
__device__ __align__(16) float g_A [BB*NCC*CCH*CCH];            // intra-chunk A (tril)
__device__ __align__(16) float g_o [(size_t)NTOK*HH];           // GLA output, later h
__device__ __align__(16) float g_go[(size_t)NTOK*HH];           // gate pre-activation
__device__ __align__(16) float g_qk[(size_t)NTOK*256];          // q/k logits (ldc=256)

// ================================ helpers ========================================
__device__ __forceinline__ float tf32r(float x) {
    uint32_t o;
    asm("cvt.rna.tf32.f32 %0, %1;" : "=r"(o) : "f"(x));
    return __uint_as_float(o);
}
__device__ __forceinline__ float4 ld4tf(const float* p) {
    float4 v = *(const float4*)p;
    v.x = tf32r(v.x); v.y = tf32r(v.y); v.z = tf32r(v.z); v.w = tf32r(v.w);
    return v;
}

// D += A*B : m16n8k8 tf32 (sm_80+ PTX, runs on plain sm_103)
__device__ __forceinline__ void mma16n8k8(float d[4],
                                          uint32_t a0, uint32_t a1, uint32_t a2, uint32_t a3,
                                          uint32_t b0, uint32_t b1) {
    asm("mma.sync.aligned.m16n8k8.row.col.f32.tf32.tf32.f32 "
        "{%0,%1,%2,%3}, {%4,%5,%6,%7}, {%8,%9}, {%0,%1,%2,%3};"
        : "+f"(d[0]), "+f"(d[1]), "+f"(d[2]), "+f"(d[3])
        : "r"(a0), "r"(a1), "r"(a2), "r"(a3), "r"(b0), "r"(b1));
}

#define SK 24

// =================================================================================
// BIG tf32 GEMM: CTA tile 128x256, BK=16, 8 warps (2x4), warp tile 64x64.
// smem m-major permuted-k (fragment pair adjacent), row stride SK=24.
// Dual-K source: A/B switch at ktile 128. Loader applies cvt.rna.tf32.
// Dynamic smem: (2*128 + 2*256) * SK * 4 = 73728 bytes.
// =================================================================================
#define BIG_SMEM ((2*128 + 2*256)*SK*4)

__global__ void __launch_bounds__(256, 1) gemm_big_kernel(
    const float* __restrict__ A1, const float* __restrict__ B1,
    const float* __restrict__ A2, const float* __restrict__ B2,
    float* __restrict__ Cmat, int nk, int ldc)
{
    extern __shared__ float sm[];
    // As stage s: sm + s*128*SK ; Bs stage s: sm + 2*128*SK + s*256*SK
    float* Asm[2] = { sm,            sm + 128*SK };
    float* Bsm[2] = { sm + 256*SK,   sm + 256*SK + 256*SK };

    const int tid = threadIdx.x;
    const int m0 = blockIdx.y * 128;
    const int n0 = blockIdx.x * 256;
    const int row = tid >> 2;            // 0..63
    const int kk4 = (tid & 3) << 2;      // 0,4,8,12
    const int pbase = ((kk4 >> 2) & 1) + (kk4 & 8);
    const int warp = tid >> 5, lane = tid & 31;
    const int wm = (warp & 1) * 64;
    const int wn = (warp >> 1) * 64;
    const int g = lane >> 2, t = lane & 3;

    float acc[4][8][4];
#pragma unroll
    for (int i = 0; i < 4; i++)
#pragma unroll
        for (int j = 0; j < 8; j++)
#pragma unroll
            for (int k = 0; k < 4; k++) acc[i][j][k] = 0.f;

    float4 ra0, ra1, rb0, rb1, rb2, rb3;

    // ---- load ktile 0 ----
    {
        const float* Ab = A1 + (size_t)(m0 + row) * HH + kk4;
        const float* Bb = B1 + (size_t)(n0 + row) * HH + kk4;
        ra0 = ld4tf(Ab);
        ra1 = ld4tf(Ab + (size_t)64 * HH);
        rb0 = ld4tf(Bb);
        rb1 = ld4tf(Bb + (size_t)64 * HH);
        rb2 = ld4tf(Bb + (size_t)128 * HH);
        rb3 = ld4tf(Bb + (size_t)192 * HH);
    }
#pragma unroll
    for (int j = 0; j < 4; j++) {
        Asm[0][(row)*SK     + pbase + 2*j] = ((float*)&ra0)[j];
        Asm[0][(row+64)*SK  + pbase + 2*j] = ((float*)&ra1)[j];
        Bsm[0][(row)*SK     + pbase + 2*j] = ((float*)&rb0)[j];
        Bsm[0][(row+64)*SK  + pbase + 2*j] = ((float*)&rb1)[j];
        Bsm[0][(row+128)*SK + pbase + 2*j] = ((float*)&rb2)[j];
        Bsm[0][(row+192)*SK + pbase + 2*j] = ((float*)&rb3)[j];
    }
    __syncthreads();

    for (int kt = 0; kt < nk; kt++) {
        const int cur = kt & 1;
        if (kt + 1 < nk) {
            int nx = kt + 1;
            const float* Ab; const float* Bb;
            if (nx < 128) { Ab = A1; Bb = B1; } else { Ab = A2; Bb = B2; }
            int kof = (nx & 127) * 16 + kk4;
            Ab += (size_t)(m0 + row) * HH + kof;
            Bb += (size_t)(n0 + row) * HH + kof;
            ra0 = ld4tf(Ab);
            ra1 = ld4tf(Ab + (size_t)64 * HH);
            rb0 = ld4tf(Bb);
            rb1 = ld4tf(Bb + (size_t)64 * HH);
            rb2 = ld4tf(Bb + (size_t)128 * HH);
            rb3 = ld4tf(Bb + (size_t)192 * HH);
        }

        const float* Ac = Asm[cur];
        const float* Bc = Bsm[cur];
#pragma unroll
        for (int ks = 0; ks < 2; ks++) {
            const int kb = ks*8 + 2*t;
            uint32_t a[4][4];
#pragma unroll
            for (int mt = 0; mt < 4; mt++) {
                int r = wm + mt*16 + g;
                float2 lo = *(const float2*)&Ac[r*SK + kb];
                float2 hi = *(const float2*)&Ac[(r+8)*SK + kb];
                a[mt][0] = __float_as_uint(lo.x);
                a[mt][1] = __float_as_uint(hi.x);
                a[mt][2] = __float_as_uint(lo.y);
                a[mt][3] = __float_as_uint(hi.y);
            }
            uint32_t b[8][2];
#pragma unroll
            for (int nt = 0; nt < 8; nt++) {
                int c = wn + nt*8 + g;
                float2 bb = *(const float2*)&Bc[c*SK + kb];
                b[nt][0] = __float_as_uint(bb.x);
                b[nt][1] = __float_as_uint(bb.y);
            }
#pragma unroll
            for (int mt = 0; mt < 4; mt++)
#pragma unroll
                for (int nt = 0; nt < 8; nt++)
                    mma16n8k8(acc[mt][nt],
                              a[mt][0], a[mt][1], a[mt][2], a[mt][3],
                              b[nt][0], b[nt][1]);
        }

        if (kt + 1 < nk) {
            const int nxt = cur ^ 1;
#pragma unroll
            for (int j = 0; j < 4; j++) {
                Asm[nxt][(row)*SK     + pbase + 2*j] = ((float*)&ra0)[j];
                Asm[nxt][(row+64)*SK  + pbase + 2*j] = ((float*)&ra1)[j];
                Bsm[nxt][(row)*SK     + pbase + 2*j] = ((float*)&rb0)[j];
                Bsm[nxt][(row+64)*SK  + pbase + 2*j] = ((float*)&rb1)[j];
                Bsm[nxt][(row+128)*SK + pbase + 2*j] = ((float*)&rb2)[j];
                Bsm[nxt][(row+192)*SK + pbase + 2*j] = ((float*)&rb3)[j];
            }
        }
        __syncthreads();
    }

    // ---- epilogue ----
#pragma unroll
    for (int mt = 0; mt < 4; mt++) {
        int r0 = m0 + wm + mt*16 + g;
#pragma unroll
        for (int nt = 0; nt < 8; nt++) {
            int c = n0 + wn + nt*8 + 2*t;
            *(float2*)(Cmat + (size_t)r0*ldc + c) =
                make_float2(acc[mt][nt][0], acc[mt][nt][1]);
            *(float2*)(Cmat + (size_t)(r0+8)*ldc + c) =
                make_float2(acc[mt][nt][2], acc[mt][nt][3]);
        }
    }
}

// =================================================================================
// Small tf32 GEMM (projections): CTA 128x128, 8 warps 64x32, dual-N:
// B selected by blockIdx.x (B1/B2), C col base = blockIdx.x*128.
// =================================================================================
__global__ void __launch_bounds__(256) gemm_proj_kernel(
    const float* __restrict__ A1, const float* __restrict__ B1,
    const float* __restrict__ B2,
    float* __restrict__ Cmat, int nk, int ldc)
{
    __shared__ float As[2][128*SK];
    __shared__ float Bs[2][128*SK];

    const int tid = threadIdx.x;
    const int m0 = blockIdx.y * 128;
    const int co = blockIdx.x * 128;
    const float* Bsel = blockIdx.x ? B2 : B1;
    const int row = tid >> 2;
    const int kk4 = (tid & 3) << 2;
    const int pbase = ((kk4 >> 2) & 1) + (kk4 & 8);
    const int warp = tid >> 5, lane = tid & 31;
    const int wm = (warp & 1) * 64;
    const int wn = (warp >> 1) * 32;
    const int g = lane >> 2, t = lane & 3;

    float acc[4][4][4];
#pragma unroll
    for (int i = 0; i < 4; i++)
#pragma unroll
        for (int j = 0; j < 4; j++)
#pragma unroll
            for (int k = 0; k < 4; k++) acc[i][j][k] = 0.f;

    float4 ra0, ra1, rb0, rb1;
    {
        const float* Ab = A1 + (size_t)(m0 + row) * HH + kk4;
        const float* Bb = Bsel + (size_t)row * HH + kk4;
        ra0 = ld4tf(Ab);
        ra1 = ld4tf(Ab + (size_t)64 * HH);
        rb0 = ld4tf(Bb);
        rb1 = ld4tf(Bb + (size_t)64 * HH);
    }
#pragma unroll
    for (int j = 0; j < 4; j++) {
        As[0][(row)*SK    + pbase + 2*j] = ((float*)&ra0)[j];
        As[0][(row+64)*SK + pbase + 2*j] = ((float*)&ra1)[j];
        Bs[0][(row)*SK    + pbase + 2*j] = ((float*)&rb0)[j];
        Bs[0][(row+64)*SK + pbase + 2*j] = ((float*)&rb1)[j];
    }
    __syncthreads();

    for (int kt = 0; kt < nk; kt++) {
        const int cur = kt & 1;
        if (kt + 1 < nk) {
            int kof = (kt + 1) * 16 + kk4;
            const float* Ab = A1 + (size_t)(m0 + row) * HH + kof;
            const float* Bb = Bsel + (size_t)row * HH + kof;
            ra0 = ld4tf(Ab);
            ra1 = ld4tf(Ab + (size_t)64 * HH);
            rb0 = ld4tf(Bb);
            rb1 = ld4tf(Bb + (size_t)64 * HH);
        }

#pragma unroll
        for (int ks = 0; ks < 2; ks++) {
            const int kb = ks*8 + 2*t;
            uint32_t a[4][4];
#pragma unroll
            for (int mt = 0; mt < 4; mt++) {
                int r = wm + mt*16 + g;
                float2 lo = *(const float2*)&As[cur][r*SK + kb];
                float2 hi = *(const float2*)&As[cur][(r+8)*SK + kb];
                a[mt][0] = __float_as_uint(lo.x);
                a[mt][1] = __float_as_uint(hi.x);
                a[mt][2] = __float_as_uint(lo.y);
                a[mt][3] = __float_as_uint(hi.y);
            }
            uint32_t b[4][2];
#pragma unroll
            for (int nt = 0; nt < 4; nt++) {
                int c = wn + nt*8 + g;
                float2 bb = *(const float2*)&Bs[cur][c*SK + kb];
                b[nt][0] = __float_as_uint(bb.x);
                b[nt][1] = __float_as_uint(bb.y);
            }
#pragma unroll
            for (int mt = 0; mt < 4; mt++)
#pragma unroll
                for (int nt = 0; nt < 4; nt++)
                    mma16n8k8(acc[mt][nt],
                              a[mt][0], a[mt][1], a[mt][2], a[mt][3],
                              b[nt][0], b[nt][1]);
        }

        if (kt + 1 < nk) {
            const int nxt = cur ^ 1;
#pragma unroll
            for (int j = 0; j < 4; j++) {
                As[nxt][(row)*SK    + pbase + 2*j] = ((float*)&ra0)[j];
                As[nxt][(row+64)*SK + pbase + 2*j] = ((float*)&ra1)[j];
                Bs[nxt][(row)*SK    + pbase + 2*j] = ((float*)&rb0)[j];
                Bs[nxt][(row+64)*SK + pbase + 2*j] = ((float*)&rb1)[j];
            }
        }
        __syncthreads();
    }

#pragma unroll
    for (int mt = 0; mt < 4; mt++) {
        int r0 = m0 + wm + mt*16 + g;
#pragma unroll
        for (int nt = 0; nt < 4; nt++) {
            int c = co + wn + nt*8 + 2*t;
            *(float2*)(Cmat + (size_t)r0*ldc + c) =
                make_float2(acc[mt][nt][0], acc[mt][nt][1]);
            *(float2*)(Cmat + (size_t)(r0+8)*ldc + c) =
                make_float2(acc[mt][nt][2], acc[mt][nt][3]);
        }
    }
}

// =================================================================================
// gate_kernel — per chunk: softmax(q) / sigmoid(k) / cumsum B, qe/kd/eL outputs,
// and A = (q e^{B-Bmid}) @ (k e^{Bmid-B})^T with tril mask.  grid = 128 blocks.
// =================================================================================
#define PADG 129
#define GATE_FLOATS (3*64*PADG + 3*128)
#define GATE_BYTES  (GATE_FLOATS*4)

__global__ void __launch_bounds__(256) gate_kernel()
{
    extern __shared__ float sm[];
    float* ql   = sm;                 // 64*PADG
    float* kl   = sm + 64*PADG;       // 64*PADG
    float* bs   = sm + 2*64*PADG;     // 64*PADG
    float* bmid = sm + 3*64*PADG;     // 128
    float* eBm  = bmid + 128;         // 128
    float* eBlm = bmid + 256;         // 128

    const int blk = blockIdx.x;
    const int b = blk / NCC, c = blk % NCC;
    const int tid = threadIdx.x;
    const int r0 = b*LL + c*CCH;

    for (int idx = tid; idx < 64*128; idx += 256) {
        int t = idx >> 7, d = idx & 127;
        const float* gr = g_qk + (size_t)(r0 + t) * 256;
        ql[t*PADG + d] = gr[d];
        kl[t*PADG + d] = 1.f / (1.f + __expf(-gr[128 + d]));
    }
    __syncthreads();

    if (tid < 64) {
        float* r = ql + tid*PADG;
        float m = -1e30f;
        for (int d = 0; d < 128; d++) m = fmaxf(m, r[d]);
        float s = 0.f;
        for (int d = 0; d < 128; d++) { float e = __expf(r[d] - m); r[d] = e; s += e; }
        float inv = 1.f / s;
        for (int d = 0; d < 128; d++) r[d] *= inv;
    }
    if (tid >= 128) {
        int d = tid - 128;
        float acc = 0.f;
        for (int t = 0; t < 64; t++) {
            acc += -log1pf(__expf(kl[t*PADG + d]));
            bs[t*PADG + d] = acc;
        }
        float Bm = bs[31*PADG + d];
        bmid[d] = Bm;
        eBm[d]  = __expf(Bm);
        eBlm[d] = __expf(acc - Bm);
        g_eL[blk*128 + d] = __expf(acc);
    }
    __syncthreads();

    size_t gbase = (size_t)r0 * DKK;
    for (int idx = tid; idx < 64*128; idx += 256) {
        int t = idx >> 7, d = idx & 127;
        float bv = bs[t*PADG + d] - bmid[d];
        float e1 = __expf(bv);
        float e2 = __expf(-bv);
        float q2 = ql[t*PADG + d] * e1;
        float k2 = kl[t*PADG + d] * e2;
        ql[t*PADG + d] = q2;
        kl[t*PADG + d] = k2;
        g_qe[gbase + idx] = q2 * eBm[d];
        g_kd[gbase + idx] = k2 * eBlm[d];
    }
    __syncthreads();

    const int tr = (tid >> 4) * 4;
    const int tc = (tid & 15) * 4;
    float a4[4][4];
#pragma unroll
    for (int r = 0; r < 4; r++)
#pragma unroll
        for (int cc = 0; cc < 4; cc++) a4[r][cc] = 0.f;
    for (int d = 0; d < 128; d++) {
        float qv[4], kv[4];
#pragma unroll
        for (int r = 0; r < 4; r++)  qv[r]  = ql[(tr+r)*PADG + d];
#pragma unroll
        for (int cc = 0; cc < 4; cc++) kv[cc] = kl[(tc+cc)*PADG + d];
#pragma unroll
        for (int r = 0; r < 4; r++)
#pragma unroll
            for (int cc = 0; cc < 4; cc++) a4[r][cc] += qv[r]*kv[cc];
    }
    float* Ag = g_A + (size_t)blk * CCH * CCH;
#pragma unroll
    for (int r = 0; r < 4; r++)
#pragma unroll
        for (int cc = 0; cc < 4; cc++)
            Ag[(tr+r)*64 + tc+cc] = (tr+r >= tc+cc) ? a4[r][cc] : 0.f;
}

// =================================================================================
// recurrence: chunked GLA. grid (H/32, B), 256 threads.
// =================================================================================
#define SMEM2_FLOATS (8192 + 8192 + 4096 + 2048 + 4096 + 128)
#define SMEM2_BYTES  (SMEM2_FLOATS*4)

__global__ void __launch_bounds__(256) recurrence_kernel(const float* __restrict__ x)
{
    extern __shared__ float sm[];
    float* qe_s = sm;              // 64*128
    float* kd_s = sm + 8192;       // 64*128
    float* A_s  = sm + 16384;      // 64*64
    float* v_s  = sm + 20480;      // 64*32
    float* S_s  = sm + 22528;      // 128*32
    float* eL_s = sm + 26624;      // 128

    const int b  = blockIdx.y;
    const int v0 = blockIdx.x * 32;
    const int tid = threadIdx.x;
    const int tx = tid & 15;
    const int ty = tid >> 4;
    const int vv = 2*tx;

    for (int i = tid; i < 128*32; i += 256) S_s[i] = 0.f;

    for (int c = 0; c < NCC; c++) {
        __syncthreads();
        {
            size_t base = ((size_t)(b*LL + c*CCH)) * DKK;
            for (int idx = tid*4; idx < 8192; idx += 1024) {
                *(float4*)(qe_s + idx) = *(const float4*)(g_qe + base + idx);
                *(float4*)(kd_s + idx) = *(const float4*)(g_kd + base + idx);
            }
            const float* Ag = g_A + (size_t)(b*NCC + c) * 4096;
            for (int idx = tid*4; idx < 4096; idx += 1024)
                *(float4*)(A_s + idx) = *(const float4*)(Ag + idx);
            for (int idx = tid; idx < 64*32; idx += 256) {
                int t = idx >> 5, j = idx & 31;
                v_s[idx] = x[((size_t)(b*LL + c*CCH + t)) * HH + v0 + j];
            }
            if (tid < 128) eL_s[tid] = g_eL[(b*NCC + c)*128 + tid];
        }
        __syncthreads();

        float o0[4] = {0,0,0,0}, o1[4] = {0,0,0,0};
#pragma unroll 4
        for (int j = 0; j < 64; j += 4) {
            float2 vj0 = *(float2*)(v_s + (j+0)*32 + vv);
            float2 vj1 = *(float2*)(v_s + (j+1)*32 + vv);
            float2 vj2 = *(float2*)(v_s + (j+2)*32 + vv);
            float2 vj3 = *(float2*)(v_s + (j+3)*32 + vv);
#pragma unroll
            for (int r = 0; r < 4; r++) {
                float4 a = *(float4*)(A_s + (ty + 16*r)*64 + j);
                o0[r] += a.x*vj0.x + a.y*vj1.x + a.z*vj2.x + a.w*vj3.x;
                o1[r] += a.x*vj0.y + a.y*vj1.y + a.z*vj2.y + a.w*vj3.y;
            }
        }
#pragma unroll 4
        for (int d = 0; d < 128; d += 4) {
            float2 s0 = *(float2*)(S_s + (d+0)*32 + vv);
            float2 s1 = *(float2*)(S_s + (d+1)*32 + vv);
            float2 s2 = *(float2*)(S_s + (d+2)*32 + vv);
            float2 s3 = *(float2*)(S_s + (d+3)*32 + vv);
#pragma unroll
            for (int r = 0; r < 4; r++) {
                float4 q = *(float4*)(qe_s + (ty + 16*r)*128 + d);
                o0[r] += q.x*s0.x + q.y*s1.x + q.z*s2.x + q.w*s3.x;
                o1[r] += q.x*s0.y + q.y*s1.y + q.z*s2.y + q.w*s3.y;
            }
        }
#pragma unroll
        for (int r = 0; r < 4; r++) {
            size_t row = (size_t)(b*LL + c*CCH + ty + 16*r);
            *(float2*)(g_o + row*HH + v0 + vv) = make_float2(o0[r], o1[r]);
        }

        float a0[8] = {0,0,0,0,0,0,0,0}, a1[8] = {0,0,0,0,0,0,0,0};
        for (int j = 0; j < 64; j++) {
            float2 vj = *(float2*)(v_s + j*32 + vv);
            float4 k0 = *(float4*)(kd_s + j*128 + ty*8);
            float4 k1 = *(float4*)(kd_s + j*128 + ty*8 + 4);
            a0[0] += k0.x*vj.x; a1[0] += k0.x*vj.y;
            a0[1] += k0.y*vj.x; a1[1] += k0.y*vj.y;
            a0[2] += k0.z*vj.x; a1[2] += k0.z*vj.y;
            a0[3] += k0.w*vj.x; a1[3] += k0.w*vj.y;
            a0[4] += k1.x*vj.x; a1[4] += k1.x*vj.y;
            a0[5] += k1.y*vj.x; a1[5] += k1.y*vj.y;
            a0[6] += k1.z*vj.x; a1[6] += k1.z*vj.y;
            a0[7] += k1.w*vj.x; a1[7] += k1.w*vj.y;
        }
        __syncthreads();
#pragma unroll
        for (int dd = 0; dd < 8; dd++) {
            int d = ty*8 + dd;
            float e = eL_s[d];
            S_s[d*32 + vv]     = S_s[d*32 + vv]     * e + a0[dd];
            S_s[d*32 + vv + 1] = S_s[d*32 + vv + 1] * e + a1[dd];
        }
    }
}

// =================================================================================
// rms_silu: h = rmsnorm(o)*g * silu(go)  (in-place into g_o)
// =================================================================================
__global__ void __launch_bounds__(256) rms_silu_kernel(const float* __restrict__ gnw)
{
    __shared__ float red[256];
    const size_t row = blockIdx.x;
    float* orow  = g_o  + row * HH;
    const float* gorow = g_go + row * HH;
    const int tid = threadIdx.x;

    float s = 0.f;
#pragma unroll
    for (int i = tid; i < HH/4; i += 256) {
        float4 v = ((const float4*)orow)[i];
        s += v.x*v.x + v.y*v.y + v.z*v.z + v.w*v.w;
    }
    red[tid] = s;
    __syncthreads();
    for (int off = 128; off > 0; off >>= 1) {
        if (tid < off) red[tid] += red[tid + off];
        __syncthreads();
    }
    float rinv = rsqrtf(red[0] * (1.f / (float)HH) + 1e-5f);

#pragma unroll
    for (int i = tid; i < HH/4; i += 256) {
        float4 ov = ((const float4*)orow)[i];
        float4 gv = ((const float4*)gorow)[i];
        float4 wv = ((const float4*)gnw)[i];
        float4 o4;
        { float a = ov.x * rinv * wv.x, g = gv.x; o4.x = a * (g / (1.f + __expf(-g))); }
        { float a = ov.y * rinv * wv.y, g = gv.y; o4.y = a * (g / (1.f + __expf(-g))); }
        { float a = ov.z * rinv * wv.z, g = gv.z; o4.z = a * (g / (1.f + __expf(-g))); }
        { float a = ov.w * rinv * wv.w, g = gv.w; o4.w = a * (g / (1.f + __expf(-g))); }
        ((float4*)orow)[i] = o4;
    }
}

// ================================= host side =====================================
extern "C" void kernel_launch(void* const* d_in, const int* in_sizes, int n_in,
                              void* d_out, int out_size)
{
    const float* x   = (const float*)d_in[0];
    const float* Wq  = (const float*)d_in[1];
    const float* Wk  = (const float*)d_in[2];
    const float* Wog = (const float*)d_in[3];
    const float* Wig = (const float*)d_in[4];
    const float* Wo  = (const float*)d_in[5];
    const float* gnw = (const float*)d_in[6];
    float* out = (float*)d_out;

    cudaFuncSetAttribute(gate_kernel,
                         cudaFuncAttributeMaxDynamicSharedMemorySize, GATE_BYTES);
    cudaFuncSetAttribute(recurrence_kernel,
                         cudaFuncAttributeMaxDynamicSharedMemorySize, SMEM2_BYTES);
    cudaFuncSetAttribute(gemm_big_kernel,
                         cudaFuncAttributeMaxDynamicSharedMemorySize, BIG_SMEM);

    float *p_o, *p_go, *p_qk;
    cudaGetSymbolAddress((void**)&p_o,  g_o);
    cudaGetSymbolAddress((void**)&p_go, g_go);
    cudaGetSymbolAddress((void**)&p_qk, g_qk);

    // 1) q/k logits: ql = x@Wq^T, kl = x@Wk^T  (dual-N projection GEMM)
    gemm_proj_kernel<<<dim3(2, NTOK/128), 256>>>(x, Wq, Wk, p_qk, 128, 256);
    // 2) gating precompute + intra-chunk A
    gate_kernel<<<BB*NCC, 256, GATE_BYTES>>>();
    // 3) chunked recurrence -> g_o
    recurrence_kernel<<<dim3(HH/32, BB), 256, SMEM2_BYTES>>>(x);
    // 4) go = x @ Wig^T + o @ Wog^T  (one dual-K big GEMM, K=4096)
    gemm_big_kernel<<<dim3(HH/256, NTOK/128), 256, BIG_SMEM>>>(x, Wig, p_o, Wog, p_go, 256, HH);
    // 5) h = rmsnorm(o)*g * silu(go)  (in place)
    rms_silu_kernel<<<NTOK, 256>>>(gnw);
    // 6) out = h @ Wo^T
    gemm_big_kernel<<<dim3(HH/256, NTOK/128), 256, BIG_SMEM>>>(p_o, Wo, p_o, Wo, out, 128, HH);
}

// round 13
// speedup vs baseline: 1.0126x; 1.0012x over previous
#include <cuda_runtime.h>
#include <math.h>
#include <stdint.h>

#define BB   2
#define LL   4096
#define HH   2048
#define DKK  128
#define CCH  64          // chunk length C
#define NCC  64          // chunks per batch
#define NTOK (BB*LL)     // 8192 tokens

// ---------------- scratch (static device globals; no allocation) ----------------
__device__ __align__(16) float g_qe[BB*LL*DKK];                 // q * exp(B)
__device__ __align__(16) float g_kd[BB*LL*DKK];                 // k * exp(Blast - B)
__device__ __align__(16) float g_eL[BB*NCC*DKK];                // exp(Blast)
__device__ __align__(16) float g_A [BB*NCC*CCH*CCH];            // intra-chunk A (tril)
__device__ __align__(16) float g_o [(size_t)NTOK*HH];           // GLA output, later h
__device__ __align__(16) float g_go[(size_t)NTOK*HH];           // gate pre-activation
__device__ __align__(16) float g_qk[(size_t)NTOK*256];          // q/k logits (ldc=256)

// ================================ helpers ========================================
__device__ __forceinline__ float tf32r(float x) {
    uint32_t o;
    asm("cvt.rna.tf32.f32 %0, %1;" : "=r"(o) : "f"(x));
    return __uint_as_float(o);
}
__device__ __forceinline__ float4 ld4tf(const float* p) {
    float4 v = *(const float4*)p;
    v.x = tf32r(v.x); v.y = tf32r(v.y); v.z = tf32r(v.z); v.w = tf32r(v.w);
    return v;
}

// D += A*B : m16n8k8 tf32 (sm_80+ PTX, runs on plain sm_103)
__device__ __forceinline__ void mma16n8k8(float d[4],
                                          uint32_t a0, uint32_t a1, uint32_t a2, uint32_t a3,
                                          uint32_t b0, uint32_t b1) {
    asm("mma.sync.aligned.m16n8k8.row.col.f32.tf32.tf32.f32 "
        "{%0,%1,%2,%3}, {%4,%5,%6,%7}, {%8,%9}, {%0,%1,%2,%3};"
        : "+f"(d[0]), "+f"(d[1]), "+f"(d[2]), "+f"(d[3])
        : "r"(a0), "r"(a1), "r"(a2), "r"(a3), "r"(b0), "r"(b1));
}

#define SK 24

// =================================================================================
// BIG tf32 GEMM: CTA tile 128x256, BK=16, 8 warps (2x4), warp tile 64x64.
// smem m-major permuted-k (fragment pair adjacent), row stride SK=24.
// Dual-K source: A/B switch at ktile 128. Loader applies cvt.rna.tf32.
// Dynamic smem: (2*128 + 2*256) * SK * 4 = 73728 bytes.
// =================================================================================
#define BIG_SMEM ((2*128 + 2*256)*SK*4)

__global__ void __launch_bounds__(256, 1) gemm_big_kernel(
    const float* __restrict__ A1, const float* __restrict__ B1,
    const float* __restrict__ A2, const float* __restrict__ B2,
    float* __restrict__ Cmat, int nk, int ldc)
{
    extern __shared__ float sm[];
    // As stage s: sm + s*128*SK ; Bs stage s: sm + 2*128*SK + s*256*SK
    float* Asm[2] = { sm,            sm + 128*SK };
    float* Bsm[2] = { sm + 256*SK,   sm + 256*SK + 256*SK };

    const int tid = threadIdx.x;
    const int m0 = blockIdx.y * 128;
    const int n0 = blockIdx.x * 256;
    const int row = tid >> 2;            // 0..63
    const int kk4 = (tid & 3) << 2;      // 0,4,8,12
    const int pbase = ((kk4 >> 2) & 1) + (kk4 & 8);
    const int warp = tid >> 5, lane = tid & 31;
    const int wm = (warp & 1) * 64;
    const int wn = (warp >> 1) * 64;
    const int g = lane >> 2, t = lane & 3;

    float acc[4][8][4];
#pragma unroll
    for (int i = 0; i < 4; i++)
#pragma unroll
        for (int j = 0; j < 8; j++)
#pragma unroll
            for (int k = 0; k < 4; k++) acc[i][j][k] = 0.f;

    float4 ra0, ra1, rb0, rb1, rb2, rb3;

    // ---- load ktile 0 ----
    {
        const float* Ab = A1 + (size_t)(m0 + row) * HH + kk4;
        const float* Bb = B1 + (size_t)(n0 + row) * HH + kk4;
        ra0 = ld4tf(Ab);
        ra1 = ld4tf(Ab + (size_t)64 * HH);
        rb0 = ld4tf(Bb);
        rb1 = ld4tf(Bb + (size_t)64 * HH);
        rb2 = ld4tf(Bb + (size_t)128 * HH);
        rb3 = ld4tf(Bb + (size_t)192 * HH);
    }
#pragma unroll
    for (int j = 0; j < 4; j++) {
        Asm[0][(row)*SK     + pbase + 2*j] = ((float*)&ra0)[j];
        Asm[0][(row+64)*SK  + pbase + 2*j] = ((float*)&ra1)[j];
        Bsm[0][(row)*SK     + pbase + 2*j] = ((float*)&rb0)[j];
        Bsm[0][(row+64)*SK  + pbase + 2*j] = ((float*)&rb1)[j];
        Bsm[0][(row+128)*SK + pbase + 2*j] = ((float*)&rb2)[j];
        Bsm[0][(row+192)*SK + pbase + 2*j] = ((float*)&rb3)[j];
    }
    __syncthreads();

    for (int kt = 0; kt < nk; kt++) {
        const int cur = kt & 1;
        if (kt + 1 < nk) {
            int nx = kt + 1;
            const float* Ab; const float* Bb;
            if (nx < 128) { Ab = A1; Bb = B1; } else { Ab = A2; Bb = B2; }
            int kof = (nx & 127) * 16 + kk4;
            Ab += (size_t)(m0 + row) * HH + kof;
            Bb += (size_t)(n0 + row) * HH + kof;
            ra0 = ld4tf(Ab);
            ra1 = ld4tf(Ab + (size_t)64 * HH);
            rb0 = ld4tf(Bb);
            rb1 = ld4tf(Bb + (size_t)64 * HH);
            rb2 = ld4tf(Bb + (size_t)128 * HH);
            rb3 = ld4tf(Bb + (size_t)192 * HH);
        }

        const float* Ac = Asm[cur];
        const float* Bc = Bsm[cur];
#pragma unroll
        for (int ks = 0; ks < 2; ks++) {
            const int kb = ks*8 + 2*t;
            uint32_t a[4][4];
#pragma unroll
            for (int mt = 0; mt < 4; mt++) {
                int r = wm + mt*16 + g;
                float2 lo = *(const float2*)&Ac[r*SK + kb];
                float2 hi = *(const float2*)&Ac[(r+8)*SK + kb];
                a[mt][0] = __float_as_uint(lo.x);
                a[mt][1] = __float_as_uint(hi.x);
                a[mt][2] = __float_as_uint(lo.y);
                a[mt][3] = __float_as_uint(hi.y);
            }
            uint32_t b[8][2];
#pragma unroll
            for (int nt = 0; nt < 8; nt++) {
                int c = wn + nt*8 + g;
                float2 bb = *(const float2*)&Bc[c*SK + kb];
                b[nt][0] = __float_as_uint(bb.x);
                b[nt][1] = __float_as_uint(bb.y);
            }
#pragma unroll
            for (int mt = 0; mt < 4; mt++)
#pragma unroll
                for (int nt = 0; nt < 8; nt++)
                    mma16n8k8(acc[mt][nt],
                              a[mt][0], a[mt][1], a[mt][2], a[mt][3],
                              b[nt][0], b[nt][1]);
        }

        if (kt + 1 < nk) {
            const int nxt = cur ^ 1;
#pragma unroll
            for (int j = 0; j < 4; j++) {
                Asm[nxt][(row)*SK     + pbase + 2*j] = ((float*)&ra0)[j];
                Asm[nxt][(row+64)*SK  + pbase + 2*j] = ((float*)&ra1)[j];
                Bsm[nxt][(row)*SK     + pbase + 2*j] = ((float*)&rb0)[j];
                Bsm[nxt][(row+64)*SK  + pbase + 2*j] = ((float*)&rb1)[j];
                Bsm[nxt][(row+128)*SK + pbase + 2*j] = ((float*)&rb2)[j];
                Bsm[nxt][(row+192)*SK + pbase + 2*j] = ((float*)&rb3)[j];
            }
        }
        __syncthreads();
    }

    // ---- epilogue ----
#pragma unroll
    for (int mt = 0; mt < 4; mt++) {
        int r0 = m0 + wm + mt*16 + g;
#pragma unroll
        for (int nt = 0; nt < 8; nt++) {
            int c = n0 + wn + nt*8 + 2*t;
            *(float2*)(Cmat + (size_t)r0*ldc + c) =
                make_float2(acc[mt][nt][0], acc[mt][nt][1]);
            *(float2*)(Cmat + (size_t)(r0+8)*ldc + c) =
                make_float2(acc[mt][nt][2], acc[mt][nt][3]);
        }
    }
}

// =================================================================================
// Small tf32 GEMM (projections): CTA 128x128, 8 warps 64x32, dual-N:
// B selected by blockIdx.x (B1/B2), C col base = blockIdx.x*128.
// =================================================================================
__global__ void __launch_bounds__(256) gemm_proj_kernel(
    const float* __restrict__ A1, const float* __restrict__ B1,
    const float* __restrict__ B2,
    float* __restrict__ Cmat, int nk, int ldc)
{
    __shared__ float As[2][128*SK];
    __shared__ float Bs[2][128*SK];

    const int tid = threadIdx.x;
    const int m0 = blockIdx.y * 128;
    const int co = blockIdx.x * 128;
    const float* Bsel = blockIdx.x ? B2 : B1;
    const int row = tid >> 2;
    const int kk4 = (tid & 3) << 2;
    const int pbase = ((kk4 >> 2) & 1) + (kk4 & 8);
    const int warp = tid >> 5, lane = tid & 31;
    const int wm = (warp & 1) * 64;
    const int wn = (warp >> 1) * 32;
    const int g = lane >> 2, t = lane & 3;

    float acc[4][4][4];
#pragma unroll
    for (int i = 0; i < 4; i++)
#pragma unroll
        for (int j = 0; j < 4; j++)
#pragma unroll
            for (int k = 0; k < 4; k++) acc[i][j][k] = 0.f;

    float4 ra0, ra1, rb0, rb1;
    {
        const float* Ab = A1 + (size_t)(m0 + row) * HH + kk4;
        const float* Bb = Bsel + (size_t)row * HH + kk4;
        ra0 = ld4tf(Ab);
        ra1 = ld4tf(Ab + (size_t)64 * HH);
        rb0 = ld4tf(Bb);
        rb1 = ld4tf(Bb + (size_t)64 * HH);
    }
#pragma unroll
    for (int j = 0; j < 4; j++) {
        As[0][(row)*SK    + pbase + 2*j] = ((float*)&ra0)[j];
        As[0][(row+64)*SK + pbase + 2*j] = ((float*)&ra1)[j];
        Bs[0][(row)*SK    + pbase + 2*j] = ((float*)&rb0)[j];
        Bs[0][(row+64)*SK + pbase + 2*j] = ((float*)&rb1)[j];
    }
    __syncthreads();

    for (int kt = 0; kt < nk; kt++) {
        const int cur = kt & 1;
        if (kt + 1 < nk) {
            int kof = (kt + 1) * 16 + kk4;
            const float* Ab = A1 + (size_t)(m0 + row) * HH + kof;
            const float* Bb = Bsel + (size_t)row * HH + kof;
            ra0 = ld4tf(Ab);
            ra1 = ld4tf(Ab + (size_t)64 * HH);
            rb0 = ld4tf(Bb);
            rb1 = ld4tf(Bb + (size_t)64 * HH);
        }

#pragma unroll
        for (int ks = 0; ks < 2; ks++) {
            const int kb = ks*8 + 2*t;
            uint32_t a[4][4];
#pragma unroll
            for (int mt = 0; mt < 4; mt++) {
                int r = wm + mt*16 + g;
                float2 lo = *(const float2*)&As[cur][r*SK + kb];
                float2 hi = *(const float2*)&As[cur][(r+8)*SK + kb];
                a[mt][0] = __float_as_uint(lo.x);
                a[mt][1] = __float_as_uint(hi.x);
                a[mt][2] = __float_as_uint(lo.y);
                a[mt][3] = __float_as_uint(hi.y);
            }
            uint32_t b[4][2];
#pragma unroll
            for (int nt = 0; nt < 4; nt++) {
                int c = wn + nt*8 + g;
                float2 bb = *(const float2*)&Bs[cur][c*SK + kb];
                b[nt][0] = __float_as_uint(bb.x);
                b[nt][1] = __float_as_uint(bb.y);
            }
#pragma unroll
            for (int mt = 0; mt < 4; mt++)
#pragma unroll
                for (int nt = 0; nt < 4; nt++)
                    mma16n8k8(acc[mt][nt],
                              a[mt][0], a[mt][1], a[mt][2], a[mt][3],
                              b[nt][0], b[nt][1]);
        }

        if (kt + 1 < nk) {
            const int nxt = cur ^ 1;
#pragma unroll
            for (int j = 0; j < 4; j++) {
                As[nxt][(row)*SK    + pbase + 2*j] = ((float*)&ra0)[j];
                As[nxt][(row+64)*SK + pbase + 2*j] = ((float*)&ra1)[j];
                Bs[nxt][(row)*SK    + pbase + 2*j] = ((float*)&rb0)[j];
                Bs[nxt][(row+64)*SK + pbase + 2*j] = ((float*)&rb1)[j];
            }
        }
        __syncthreads();
    }

#pragma unroll
    for (int mt = 0; mt < 4; mt++) {
        int r0 = m0 + wm + mt*16 + g;
#pragma unroll
        for (int nt = 0; nt < 4; nt++) {
            int c = co + wn + nt*8 + 2*t;
            *(float2*)(Cmat + (size_t)r0*ldc + c) =
                make_float2(acc[mt][nt][0], acc[mt][nt][1]);
            *(float2*)(Cmat + (size_t)(r0+8)*ldc + c) =
                make_float2(acc[mt][nt][2], acc[mt][nt][3]);
        }
    }
}

// =================================================================================
// gate_kernel — per chunk: softmax(q) / sigmoid(k) / cumsum B, qe/kd/eL outputs,
// and A = (q e^{B-Bmid}) @ (k e^{Bmid-B})^T with tril mask.  grid = 128 blocks.
// =================================================================================
#define PADG 129
#define GATE_FLOATS (3*64*PADG + 3*128)
#define GATE_BYTES  (GATE_FLOATS*4)

__global__ void __launch_bounds__(256) gate_kernel()
{
    extern __shared__ float sm[];
    float* ql   = sm;                 // 64*PADG
    float* kl   = sm + 64*PADG;       // 64*PADG
    float* bs   = sm + 2*64*PADG;     // 64*PADG
    float* bmid = sm + 3*64*PADG;     // 128
    float* eBm  = bmid + 128;         // 128
    float* eBlm = bmid + 256;         // 128

    const int blk = blockIdx.x;
    const int b = blk / NCC, c = blk % NCC;
    const int tid = threadIdx.x;
    const int r0 = b*LL + c*CCH;

    for (int idx = tid; idx < 64*128; idx += 256) {
        int t = idx >> 7, d = idx & 127;
        const float* gr = g_qk + (size_t)(r0 + t) * 256;
        ql[t*PADG + d] = gr[d];
        kl[t*PADG + d] = 1.f / (1.f + __expf(-gr[128 + d]));
    }
    __syncthreads();

    if (tid < 64) {
        float* r = ql + tid*PADG;
        float m = -1e30f;
        for (int d = 0; d < 128; d++) m = fmaxf(m, r[d]);
        float s = 0.f;
        for (int d = 0; d < 128; d++) { float e = __expf(r[d] - m); r[d] = e; s += e; }
        float inv = 1.f / s;
        for (int d = 0; d < 128; d++) r[d] *= inv;
    }
    if (tid >= 128) {
        int d = tid - 128;
        float acc = 0.f;
        for (int t = 0; t < 64; t++) {
            acc += -log1pf(__expf(kl[t*PADG + d]));
            bs[t*PADG + d] = acc;
        }
        float Bm = bs[31*PADG + d];
        bmid[d] = Bm;
        eBm[d]  = __expf(Bm);
        eBlm[d] = __expf(acc - Bm);
        g_eL[blk*128 + d] = __expf(acc);
    }
    __syncthreads();

    size_t gbase = (size_t)r0 * DKK;
    for (int idx = tid; idx < 64*128; idx += 256) {
        int t = idx >> 7, d = idx & 127;
        float bv = bs[t*PADG + d] - bmid[d];
        float e1 = __expf(bv);
        float e2 = __expf(-bv);
        float q2 = ql[t*PADG + d] * e1;
        float k2 = kl[t*PADG + d] * e2;
        ql[t*PADG + d] = q2;
        kl[t*PADG + d] = k2;
        g_qe[gbase + idx] = q2 * eBm[d];
        g_kd[gbase + idx] = k2 * eBlm[d];
    }
    __syncthreads();

    const int tr = (tid >> 4) * 4;
    const int tc = (tid & 15) * 4;
    float a4[4][4];
#pragma unroll
    for (int r = 0; r < 4; r++)
#pragma unroll
        for (int cc = 0; cc < 4; cc++) a4[r][cc] = 0.f;
    for (int d = 0; d < 128; d++) {
        float qv[4], kv[4];
#pragma unroll
        for (int r = 0; r < 4; r++)  qv[r]  = ql[(tr+r)*PADG + d];
#pragma unroll
        for (int cc = 0; cc < 4; cc++) kv[cc] = kl[(tc+cc)*PADG + d];
#pragma unroll
        for (int r = 0; r < 4; r++)
#pragma unroll
            for (int cc = 0; cc < 4; cc++) a4[r][cc] += qv[r]*kv[cc];
    }
    float* Ag = g_A + (size_t)blk * CCH * CCH;
#pragma unroll
    for (int r = 0; r < 4; r++)
#pragma unroll
        for (int cc = 0; cc < 4; cc++)
            Ag[(tr+r)*64 + tc+cc] = (tr+r >= tc+cc) ? a4[r][cc] : 0.f;
}

// =================================================================================
// recurrence: chunked GLA. grid (H/32, B), 256 threads.
// =================================================================================
#define SMEM2_FLOATS (8192 + 8192 + 4096 + 2048 + 4096 + 128)
#define SMEM2_BYTES  (SMEM2_FLOATS*4)

__global__ void __launch_bounds__(256) recurrence_kernel(const float* __restrict__ x)
{
    extern __shared__ float sm[];
    float* qe_s = sm;              // 64*128
    float* kd_s = sm + 8192;       // 64*128
    float* A_s  = sm + 16384;      // 64*64
    float* v_s  = sm + 20480;      // 64*32
    float* S_s  = sm + 22528;      // 128*32
    float* eL_s = sm + 26624;      // 128

    const int b  = blockIdx.y;
    const int v0 = blockIdx.x * 32;
    const int tid = threadIdx.x;
    const int tx = tid & 15;
    const int ty = tid >> 4;
    const int vv = 2*tx;

    for (int i = tid; i < 128*32; i += 256) S_s[i] = 0.f;

    for (int c = 0; c < NCC; c++) {
        __syncthreads();
        {
            size_t base = ((size_t)(b*LL + c*CCH)) * DKK;
            for (int idx = tid*4; idx < 8192; idx += 1024) {
                *(float4*)(qe_s + idx) = *(const float4*)(g_qe + base + idx);
                *(float4*)(kd_s + idx) = *(const float4*)(g_kd + base + idx);
            }
            const float* Ag = g_A + (size_t)(b*NCC + c) * 4096;
            for (int idx = tid*4; idx < 4096; idx += 1024)
                *(float4*)(A_s + idx) = *(const float4*)(Ag + idx);
            for (int idx = tid; idx < 64*32; idx += 256) {
                int t = idx >> 5, j = idx & 31;
                v_s[idx] = x[((size_t)(b*LL + c*CCH + t)) * HH + v0 + j];
            }
            if (tid < 128) eL_s[tid] = g_eL[(b*NCC + c)*128 + tid];
        }
        __syncthreads();

        float o0[4] = {0,0,0,0}, o1[4] = {0,0,0,0};
#pragma unroll 4
        for (int j = 0; j < 64; j += 4) {
            float2 vj0 = *(float2*)(v_s + (j+0)*32 + vv);
            float2 vj1 = *(float2*)(v_s + (j+1)*32 + vv);
            float2 vj2 = *(float2*)(v_s + (j+2)*32 + vv);
            float2 vj3 = *(float2*)(v_s + (j+3)*32 + vv);
#pragma unroll
            for (int r = 0; r < 4; r++) {
                float4 a = *(float4*)(A_s + (ty + 16*r)*64 + j);
                o0[r] += a.x*vj0.x + a.y*vj1.x + a.z*vj2.x + a.w*vj3.x;
                o1[r] += a.x*vj0.y + a.y*vj1.y + a.z*vj2.y + a.w*vj3.y;
            }
        }
#pragma unroll 4
        for (int d = 0; d < 128; d += 4) {
            float2 s0 = *(float2*)(S_s + (d+0)*32 + vv);
            float2 s1 = *(float2*)(S_s + (d+1)*32 + vv);
            float2 s2 = *(float2*)(S_s + (d+2)*32 + vv);
            float2 s3 = *(float2*)(S_s + (d+3)*32 + vv);
#pragma unroll
            for (int r = 0; r < 4; r++) {
                float4 q = *(float4*)(qe_s + (ty + 16*r)*128 + d);
                o0[r] += q.x*s0.x + q.y*s1.x + q.z*s2.x + q.w*s3.x;
                o1[r] += q.x*s0.y + q.y*s1.y + q.z*s2.y + q.w*s3.y;
            }
        }
#pragma unroll
        for (int r = 0; r < 4; r++) {
            size_t row = (size_t)(b*LL + c*CCH + ty + 16*r);
            *(float2*)(g_o + row*HH + v0 + vv) = make_float2(o0[r], o1[r]);
        }

        float a0[8] = {0,0,0,0,0,0,0,0}, a1[8] = {0,0,0,0,0,0,0,0};
        for (int j = 0; j < 64; j++) {
            float2 vj = *(float2*)(v_s + j*32 + vv);
            float4 k0 = *(float4*)(kd_s + j*128 + ty*8);
            float4 k1 = *(float4*)(kd_s + j*128 + ty*8 + 4);
            a0[0] += k0.x*vj.x; a1[0] += k0.x*vj.y;
            a0[1] += k0.y*vj.x; a1[1] += k0.y*vj.y;
            a0[2] += k0.z*vj.x; a1[2] += k0.z*vj.y;
            a0[3] += k0.w*vj.x; a1[3] += k0.w*vj.y;
            a0[4] += k1.x*vj.x; a1[4] += k1.x*vj.y;
            a0[5] += k1.y*vj.x; a1[5] += k1.y*vj.y;
            a0[6] += k1.z*vj.x; a1[6] += k1.z*vj.y;
            a0[7] += k1.w*vj.x; a1[7] += k1.w*vj.y;
        }
        __syncthreads();
#pragma unroll
        for (int dd = 0; dd < 8; dd++) {
            int d = ty*8 + dd;
            float e = eL_s[d];
            S_s[d*32 + vv]     = S_s[d*32 + vv]     * e + a0[dd];
            S_s[d*32 + vv + 1] = S_s[d*32 + vv + 1] * e + a1[dd];
        }
    }
}

// =================================================================================
// rms_silu: h = rmsnorm(o)*g * silu(go)  (in-place into g_o)
// =================================================================================
__global__ void __launch_bounds__(256) rms_silu_kernel(const float* __restrict__ gnw)
{
    __shared__ float red[256];
    const size_t row = blockIdx.x;
    float* orow  = g_o  + row * HH;
    const float* gorow = g_go + row * HH;
    const int tid = threadIdx.x;

    float s = 0.f;
#pragma unroll
    for (int i = tid; i < HH/4; i += 256) {
        float4 v = ((const float4*)orow)[i];
        s += v.x*v.x + v.y*v.y + v.z*v.z + v.w*v.w;
    }
    red[tid] = s;
    __syncthreads();
    for (int off = 128; off > 0; off >>= 1) {
        if (tid < off) red[tid] += red[tid + off];
        __syncthreads();
    }
    float rinv = rsqrtf(red[0] * (1.f / (float)HH) + 1e-5f);

#pragma unroll
    for (int i = tid; i < HH/4; i += 256) {
        float4 ov = ((const float4*)orow)[i];
        float4 gv = ((const float4*)gorow)[i];
        float4 wv = ((const float4*)gnw)[i];
        float4 o4;
        { float a = ov.x * rinv * wv.x, g = gv.x; o4.x = a * (g / (1.f + __expf(-g))); }
        { float a = ov.y * rinv * wv.y, g = gv.y; o4.y = a * (g / (1.f + __expf(-g))); }
        { float a = ov.z * rinv * wv.z, g = gv.z; o4.z = a * (g / (1.f + __expf(-g))); }
        { float a = ov.w * rinv * wv.w, g = gv.w; o4.w = a * (g / (1.f + __expf(-g))); }
        ((float4*)orow)[i] = o4;
    }
}

// ================================= host side =====================================
extern "C" void kernel_launch(void* const* d_in, const int* in_sizes, int n_in,
                              void* d_out, int out_size)
{
    const float* x   = (const float*)d_in[0];
    const float* Wq  = (const float*)d_in[1];
    const float* Wk  = (const float*)d_in[2];
    const float* Wog = (const float*)d_in[3];
    const float* Wig = (const float*)d_in[4];
    const float* Wo  = (const float*)d_in[5];
    const float* gnw = (const float*)d_in[6];
    float* out = (float*)d_out;

    cudaFuncSetAttribute(gate_kernel,
                         cudaFuncAttributeMaxDynamicSharedMemorySize, GATE_BYTES);
    cudaFuncSetAttribute(recurrence_kernel,
                         cudaFuncAttributeMaxDynamicSharedMemorySize, SMEM2_BYTES);
    cudaFuncSetAttribute(gemm_big_kernel,
                         cudaFuncAttributeMaxDynamicSharedMemorySize, BIG_SMEM);

    float *p_o, *p_go, *p_qk;
    cudaGetSymbolAddress((void**)&p_o,  g_o);
    cudaGetSymbolAddress((void**)&p_go, g_go);
    cudaGetSymbolAddress((void**)&p_qk, g_qk);

    // 1) q/k logits: ql = x@Wq^T, kl = x@Wk^T  (dual-N projection GEMM)
    gemm_proj_kernel<<<dim3(2, NTOK/128), 256>>>(x, Wq, Wk, p_qk, 128, 256);
    // 2) gating precompute + intra-chunk A
    gate_kernel<<<BB*NCC, 256, GATE_BYTES>>>();
    // 3) chunked recurrence -> g_o
    recurrence_kernel<<<dim3(HH/32, BB), 256, SMEM2_BYTES>>>(x);
    // 4) go = x @ Wig^T + o @ Wog^T  (one dual-K big GEMM, K=4096)
    gemm_big_kernel<<<dim3(HH/256, NTOK/128), 256, BIG_SMEM>>>(x, Wig, p_o, Wog, p_go, 256, HH);
    // 5) h = rmsnorm(o)*g * silu(go)  (in place)
    rms_silu_kernel<<<NTOK, 256>>>(gnw);
    // 6) out = h @ Wo^T
    gemm_big_kernel<<<dim3(HH/256, NTOK/128), 256, BIG_SMEM>>>(p_o, Wo, p_o, Wo, out, 128, HH);
}